// round 12
// baseline (speedup 1.0000x reference)
#include <cuda_runtime.h>
#include <cstdint>

#define DIMS   256
#define BATCH  2048
#define NPAIR  32896              // 256*257/2 upper-triangle pairs
#define NROWS  33280              // 260 tiles * 128 rows
#define BM     128
#define BN     256
#define THREADS 512
#define STAGE_BYTES (BM * 128 * 4)               // 64 KB: K=128 half, 4 sub-tiles
#define SMEM_BYTES  (2 * STAGE_BYTES + BN * 4)   // 129 KB

// ---- device scratch (allocation-free) ----
__device__ float    g_c3p[NROWS * DIMS];         // 34 MB packed A, row-major, tf32-rounded
__device__ uint32_t g_pairIdx[NROWS];            // (i<<16)|j per row
// B fragment-major: word = ((ng*16 + kp)*32 + lane)*4 + r
//   ng=b>>3, kp=k>>4, lane=(b&7)*4+(k&3), r=((k>>3)&1)*2+((k&7)>>2)
__device__ float    g_relf[BATCH * DIMS];        // 2 MB, tf32-rounded
__device__ float    g_relT[(DIMS + 1) * BATCH];  // rel^T exact; row 256 = 1.0

static __device__ __forceinline__ float f2tf32f(float f) {
    uint32_t r;
    asm("cvt.rna.tf32.f32 %0, %1;" : "=r"(r) : "f"(f));
    return __uint_as_float(r);
}

#define MMA_TF32(C, A0, A1, A2, A3, B0, B1)                                   \
    asm volatile(                                                             \
        "mma.sync.aligned.m16n8k8.row.col.f32.tf32.tf32.f32 "                 \
        "{%0,%1,%2,%3}, {%4,%5,%6,%7}, {%8,%9}, {%0,%1,%2,%3};"               \
        : "+f"((C)[0]), "+f"((C)[1]), "+f"((C)[2]), "+f"((C)[3])              \
        : "r"(A0), "r"(A1), "r"(A2), "r"(A3), "r"(B0), "r"(B1))

#define LDSM4(R, addr)                                                        \
    asm volatile("ldmatrix.sync.aligned.m8n8.x4.shared.b16 {%0,%1,%2,%3}, [%4];" \
        : "=r"((R)[0]), "=r"((R)[1]), "=r"((R)[2]), "=r"((R)[3])              \
        : "r"(addr))

static __device__ __forceinline__ void cp16(uint32_t dst, const void* gsrc) {
    asm volatile("cp.async.cg.shared.global [%0], [%1], 16;"
                 :: "r"(dst), "l"(gsrc) : "memory");
}
#define CP_COMMIT() asm volatile("cp.async.commit_group;" ::: "memory")
#define CP_WAIT(n)  asm volatile("cp.async.wait_group %0;" :: "n"(n) : "memory")

static __device__ __forceinline__ uint32_t smem_u32(const void* p) {
    uint32_t a;
    asm("{ .reg .u64 t; cvta.to.shared.u64 t, %1; cvt.u32.u64 %0, t; }" : "=r"(a) : "l"(p));
    return a;
}

// ---------------------------------------------------------------------------
// Prep: g_relf fragments + g_relT weights + out init (merged)
// ---------------------------------------------------------------------------
__global__ void prep_rel_kernel(const float* __restrict__ x,
                                const float* __restrict__ offsets,
                                const float* __restrict__ c0p,
                                float* __restrict__ out) {
    int idx = blockIdx.x * blockDim.x + threadIdx.x;   // k*BATCH + b
    int k = idx / BATCH;
    int b = idx % BATCH;
    if (k < DIMS) {
        float r = x[b * DIMS + k] - offsets[k];
        g_relT[idx] = r;
        int ng = b >> 3, kp = k >> 4;
        int lane = (b & 7) * 4 + (k & 3);
        int rr = (((k >> 3) & 1) << 1) | ((k & 7) >> 2);
        ((uint32_t*)g_relf)[((ng * 16 + kp) * 32 + lane) * 4 + rr] =
            __float_as_uint(f2tf32f(r));
    } else {
        g_relT[idx] = 1.0f;
        out[b] = c0p[0];
    }
}

// ---------------------------------------------------------------------------
// Pack (coalesced): row-major symmetrized A + pair index table.
// ---------------------------------------------------------------------------
__global__ void pack_kernel(const float* __restrict__ c3,
                            const float* __restrict__ c2,
                            const float* __restrict__ c1) {
    int j = blockIdx.x, i = blockIdx.y, t = threadIdx.x;
    int p;
    float4 v;
    uint32_t pidx;
    if (i < 256) {
        if (j < i) return;
        p = i * 256 - (i * (i - 1)) / 2 + (j - i);
        v = *(const float4*)(c3 + ((size_t)(i * 256 + j)) * DIMS + t * 4);
        if (i != j) {
            float4 w = *(const float4*)(c3 + ((size_t)(j * 256 + i)) * DIMS + t * 4);
            v.x += w.x; v.y += w.y; v.z += w.z; v.w += w.w;
        }
        pidx = ((uint32_t)i << 16) | (uint32_t)j;
    } else if (i == 256) {
        p = NPAIR + j;
        v = *(const float4*)(c2 + (size_t)j * DIMS + t * 4);
        pidx = (256u << 16) | (uint32_t)j;
    } else {
        if (j == 0) {
            p = NPAIR + 256;
            v = *(const float4*)(c1 + t * 4);
        } else if (j < 128) {
            p = NPAIR + 256 + j;
            v = make_float4(0.f, 0.f, 0.f, 0.f);
        } else return;
        pidx = (256u << 16) | 256u;
    }
    v.x = f2tf32f(v.x); v.y = f2tf32f(v.y); v.z = f2tf32f(v.z); v.w = f2tf32f(v.w);
    *(float4*)(g_c3p + (size_t)p * DIMS + t * 4) = v;
    if (t == 0) g_pairIdx[p] = pidx;
}

// ---------------------------------------------------------------------------
// Main: 512 threads, 16 warps = 4M x 4N (32x64 warp tiles).
// A: cp.async, 2 stages of K=128 -> 2 barriers; LDSM once per k16 (A held).
// B: direct GMEM fragments, nsl-half pipelined.
// ---------------------------------------------------------------------------
__global__ void __launch_bounds__(THREADS) taylor_mma_kernel(
    float* __restrict__ out) {

    extern __shared__ char smem[];
    const uint32_t sb = smem_u32(smem);
    float* sred = (float*)(smem + 2 * STAGE_BYTES);

    const int tid  = threadIdx.x;
    const int lane = tid & 31, wid = tid >> 5;
    const int warpM = wid & 3, warpN = wid >> 2;   // 4 x 4 warps
    const int g = lane >> 2, tig = lane & 3;
    const int p0 = blockIdx.x * BM;
    const int b0 = blockIdx.y * BN;

    if (tid < BN) sred[tid] = 0.f;

    // ---- A cp.async coords (16KB sub-tile, 512 thr => 2 cp16/thread) ----
    const float* Ag = g_c3p + (size_t)p0 * DIMS;
    uint32_t cpdst[2];
    const float* cpsrc[2];
#pragma unroll
    for (int it = 0; it < 2; it++) {
        int idx = tid + it * THREADS;
        int row = idx >> 3, seg = idx & 7;
        cpdst[it] = row * 128 + ((seg ^ (row & 7)) << 4);
        cpsrc[it] = Ag + (size_t)row * DIMS + seg * 4;
    }
    auto cp_stage = [&](int stage) {
        const uint32_t s = sb + stage * STAGE_BYTES;
#pragma unroll
        for (int q = 0; q < 4; q++) {
            const int k0 = stage * 128 + q * 32;
#pragma unroll
            for (int it = 0; it < 2; it++)
                cp16(s + q * 16384 + cpdst[it], cpsrc[it] + k0);
        }
    };

    // ---- B fragment pointer; 8 n-slots per warp (warp tile N=64) ----
    const uint4* bptr = (const uint4*)g_relf
                      + ((size_t)(b0 >> 3) + warpN * 8) * 512 + lane;

    // ---- LDSM addressing: 2 msl (warp tile M=32) ----
    int aoff[2], axor[2];
#pragma unroll
    for (int msl = 0; msl < 2; msl++) {
        int rowA = warpM * 32 + msl * 16 + ((lane >> 3) & 1) * 8 + (lane & 7);
        aoff[msl] = rowA * 128;
        axor[msl] = rowA & 7;
    }
    const int kcA = (lane >> 4) & 1;

    float acc[2][8][4];
#pragma unroll
    for (int m = 0; m < 2; m++)
#pragma unroll
        for (int n = 0; n < 8; n++)
#pragma unroll
            for (int r = 0; r < 4; r++) acc[m][n][r] = 0.f;

    uint4 Bh0[4], Bh1[4];       // nsl halves
    uint32_t a[2][2][4];        // [ks2][msl][4] — A held across the k16

    // prologue: both K halves in flight
    cp_stage(0); CP_COMMIT();
    cp_stage(1); CP_COMMIT();

#define LDBH(BB, kp, nb)                                                      \
    do {                                                                      \
        _Pragma("unroll")                                                     \
        for (int q_ = 0; q_ < 4; q_++)                                        \
            (BB)[q_] = __ldg(bptr + ((nb) + q_) * 512 + (kp) * 32);           \
    } while (0)

#define LDA_K16(As, KSBASE)                                                   \
    do {                                                                      \
        _Pragma("unroll")                                                     \
        for (int ks2_ = 0; ks2_ < 2; ++ks2_) {                                \
            const int ks_ = (KSBASE) + ks2_;                                  \
            _Pragma("unroll")                                                 \
            for (int msl_ = 0; msl_ < 2; ++msl_)                              \
                LDSM4(a[ks2_][msl_], (As) + aoff[msl_] +                      \
                      ((((ks_ << 1) | kcA) ^ axor[msl_]) << 4));              \
        }                                                                     \
    } while (0)

#define MMA_HALF(BB, NB)                                                      \
    do {                                                                      \
        _Pragma("unroll")                                                     \
        for (int ks2_ = 0; ks2_ < 2; ++ks2_) {                                \
            _Pragma("unroll")                                                 \
            for (int q_ = 0; q_ < 4; ++q_) {                                  \
                uint32_t b0v = ks2_ ? (BB)[q_].z : (BB)[q_].x;                \
                uint32_t b1v = ks2_ ? (BB)[q_].w : (BB)[q_].y;                \
                _Pragma("unroll")                                             \
                for (int msl_ = 0; msl_ < 2; ++msl_)                          \
                    MMA_TF32(acc[msl_][(NB) + q_],                            \
                             a[ks2_][msl_][0], a[ks2_][msl_][1],              \
                             a[ks2_][msl_][2], a[ks2_][msl_][3], b0v, b1v);   \
            }                                                                 \
        }                                                                     \
    } while (0)

    LDBH(Bh0, 0, 0);
    CP_WAIT(1);
    __syncthreads();                       // barrier #1: stage 0 resident

#pragma unroll
    for (int stage = 0; stage < 2; ++stage) {
        const uint32_t S = sb + stage * STAGE_BYTES;
#pragma unroll
        for (int q = 0; q < 4; ++q) {
            const uint32_t As = S + q * 16384;
#pragma unroll
            for (int h = 0; h < 2; ++h) {   // two k16 per 32-k sub-tile
                const int kp = stage * 8 + q * 2 + h;
                LDA_K16(As, h * 2);
                LDBH(Bh1, kp, 4);           // second nsl-half of this kp
                MMA_HALF(Bh0, 0);
                if (kp + 1 < 16) LDBH(Bh0, kp + 1, 0);
                MMA_HALF(Bh1, 4);
            }
        }
        if (stage == 0) {
            CP_WAIT(0);
            __syncthreads();               // barrier #2: stage 1 resident
        }
    }

    // ---- epilogue: sred[col] += sum_m D[m,col] * r_i(m)[b] * r_j(m)[b] ----
    const float* wi[2][2];
    const float* wj[2][2];
#pragma unroll
    for (int msl = 0; msl < 2; ++msl)
#pragma unroll
        for (int h = 0; h < 2; ++h) {
            int rloc = warpM * 32 + msl * 16 + h * 8 + g;
            uint32_t pij = g_pairIdx[p0 + rloc];
            wi[msl][h] = g_relT + (size_t)(pij >> 16) * BATCH + b0;
            wj[msl][h] = g_relT + (size_t)(pij & 0xFFFF) * BATCH + b0;
        }

#pragma unroll
    for (int nsl = 0; nsl < 8; ++nsl) {
        const int coln = warpN * 64 + nsl * 8 + tig * 2;
        float s0 = 0.f, s1 = 0.f;
#pragma unroll
        for (int msl = 0; msl < 2; ++msl) {
#pragma unroll
            for (int h = 0; h < 2; ++h) {
                float2 aw = *(const float2*)(wi[msl][h] + coln);
                float2 bw = *(const float2*)(wj[msl][h] + coln);
                s0 += acc[msl][nsl][2 * h]     * aw.x * bw.x;
                s1 += acc[msl][nsl][2 * h + 1] * aw.y * bw.y;
            }
        }
#pragma unroll
        for (int o = 4; o <= 16; o <<= 1) {
            s0 += __shfl_xor_sync(0xFFFFFFFFu, s0, o);
            s1 += __shfl_xor_sync(0xFFFFFFFFu, s1, o);
        }
        if (g == 0) {
            atomicAdd(&sred[coln],     s0);
            atomicAdd(&sred[coln + 1], s1);
        }
    }
    __syncthreads();

    if (tid < BN) atomicAdd(out + b0 + tid, sred[tid]);
}

// ---------------------------------------------------------------------------
extern "C" void kernel_launch(void* const* d_in, const int* in_sizes, int n_in,
                              void* d_out, int out_size) {
    const float* x       = (const float*)d_in[0];
    const float* offsets = (const float*)d_in[1];
    const float* coeff0  = (const float*)d_in[2];
    const float* coeff1  = (const float*)d_in[3];
    const float* coeff2  = (const float*)d_in[4];
    const float* coeff3  = (const float*)d_in[5];
    float* out = (float*)d_out;

    cudaFuncSetAttribute(taylor_mma_kernel,
                         cudaFuncAttributeMaxDynamicSharedMemorySize, SMEM_BYTES);

    prep_rel_kernel<<<((DIMS + 1) * BATCH) / 256, 256>>>(x, offsets, coeff0, out);

    dim3 pgrid(256, 258);
    pack_kernel<<<pgrid, 64>>>(coeff3, coeff2, coeff1);

    dim3 grid(NROWS / BM, BATCH / BN);   // (260, 8)
    taylor_mma_kernel<<<grid, THREADS, SMEM_BYTES>>>(out);
}

// round 13
// speedup vs baseline: 1.0374x; 1.0374x over previous
#include <cuda_runtime.h>
#include <cstdint>

#define DIMS   256
#define BATCH  2048
#define NPAIR  32896              // 256*257/2 upper-triangle pairs
#define NROWS  33280              // 260 tiles * 128 rows
#define BM     128
#define BN     256
#define THREADS 256
#define STAGE_BYTES (BM * 128 * 4)               // 64 KB: K=128 half, 4 sub-tiles
#define SMEM_BYTES  (2 * STAGE_BYTES + BN * 4)   // 129 KB

// ---- device scratch (allocation-free) ----
__device__ float    g_c3p[NROWS * DIMS];         // 34 MB packed A, row-major, tf32-rounded
__device__ uint32_t g_pairIdx[NROWS];            // (i<<16)|j per row
// B fragment-major: word = ((ng*16 + kp)*32 + lane)*4 + r
//   ng=b>>3, kp=k>>4, lane=(b&7)*4+(k&3), r=((k>>3)&1)*2+((k&7)>>2)
__device__ float    g_relf[BATCH * DIMS];        // 2 MB, tf32-rounded
__device__ float    g_relT[(DIMS + 1) * BATCH];  // rel^T exact; row 256 = 1.0

static __device__ __forceinline__ float f2tf32f(float f) {
    uint32_t r;
    asm("cvt.rna.tf32.f32 %0, %1;" : "=r"(r) : "f"(f));
    return __uint_as_float(r);
}

#define MMA_TF32(C, A0, A1, A2, A3, B0, B1)                                   \
    asm volatile(                                                             \
        "mma.sync.aligned.m16n8k8.row.col.f32.tf32.tf32.f32 "                 \
        "{%0,%1,%2,%3}, {%4,%5,%6,%7}, {%8,%9}, {%0,%1,%2,%3};"               \
        : "+f"((C)[0]), "+f"((C)[1]), "+f"((C)[2]), "+f"((C)[3])              \
        : "r"(A0), "r"(A1), "r"(A2), "r"(A3), "r"(B0), "r"(B1))

#define LDSM4(R, addr)                                                        \
    asm volatile("ldmatrix.sync.aligned.m8n8.x4.shared.b16 {%0,%1,%2,%3}, [%4];" \
        : "=r"((R)[0]), "=r"((R)[1]), "=r"((R)[2]), "=r"((R)[3])              \
        : "r"(addr))

static __device__ __forceinline__ void cp16(uint32_t dst, const void* gsrc) {
    asm volatile("cp.async.cg.shared.global [%0], [%1], 16;"
                 :: "r"(dst), "l"(gsrc) : "memory");
}
#define CP_COMMIT() asm volatile("cp.async.commit_group;" ::: "memory")
#define CP_WAIT(n)  asm volatile("cp.async.wait_group %0;" :: "n"(n) : "memory")

static __device__ __forceinline__ uint32_t smem_u32(const void* p) {
    uint32_t a;
    asm("{ .reg .u64 t; cvta.to.shared.u64 t, %1; cvt.u32.u64 %0, t; }" : "=r"(a) : "l"(p));
    return a;
}

// ---------------------------------------------------------------------------
// Prep: g_relf fragments + g_relT weights + out init (merged)
// ---------------------------------------------------------------------------
__global__ void prep_rel_kernel(const float* __restrict__ x,
                                const float* __restrict__ offsets,
                                const float* __restrict__ c0p,
                                float* __restrict__ out) {
    int idx = blockIdx.x * blockDim.x + threadIdx.x;   // k*BATCH + b
    int k = idx / BATCH;
    int b = idx % BATCH;
    if (k < DIMS) {
        float r = x[b * DIMS + k] - offsets[k];
        g_relT[idx] = r;
        int ng = b >> 3, kp = k >> 4;
        int lane = (b & 7) * 4 + (k & 3);
        int rr = (((k >> 3) & 1) << 1) | ((k & 7) >> 2);
        ((uint32_t*)g_relf)[((ng * 16 + kp) * 32 + lane) * 4 + rr] =
            __float_as_uint(f2tf32f(r));
    } else {
        g_relT[idx] = 1.0f;
        out[b] = c0p[0];
    }
}

// ---------------------------------------------------------------------------
// Pack (coalesced): row-major symmetrized A + pair index table.
// ---------------------------------------------------------------------------
__global__ void pack_kernel(const float* __restrict__ c3,
                            const float* __restrict__ c2,
                            const float* __restrict__ c1) {
    int j = blockIdx.x, i = blockIdx.y, t = threadIdx.x;
    int p;
    float4 v;
    uint32_t pidx;
    if (i < 256) {
        if (j < i) return;
        p = i * 256 - (i * (i - 1)) / 2 + (j - i);
        v = *(const float4*)(c3 + ((size_t)(i * 256 + j)) * DIMS + t * 4);
        if (i != j) {
            float4 w = *(const float4*)(c3 + ((size_t)(j * 256 + i)) * DIMS + t * 4);
            v.x += w.x; v.y += w.y; v.z += w.z; v.w += w.w;
        }
        pidx = ((uint32_t)i << 16) | (uint32_t)j;
    } else if (i == 256) {
        p = NPAIR + j;
        v = *(const float4*)(c2 + (size_t)j * DIMS + t * 4);
        pidx = (256u << 16) | (uint32_t)j;
    } else {
        if (j == 0) {
            p = NPAIR + 256;
            v = *(const float4*)(c1 + t * 4);
        } else if (j < 128) {
            p = NPAIR + 256 + j;
            v = make_float4(0.f, 0.f, 0.f, 0.f);
        } else return;
        pidx = (256u << 16) | 256u;
    }
    v.x = f2tf32f(v.x); v.y = f2tf32f(v.y); v.z = f2tf32f(v.z); v.w = f2tf32f(v.w);
    *(float4*)(g_c3p + (size_t)p * DIMS + t * 4) = v;
    if (t == 0) g_pairIdx[p] = pidx;
}

// ---------------------------------------------------------------------------
// Main: 256 threads, 8 warps = 2M x 4N (64x64 warp tiles, acc 128 regs).
// A: cp.async, 2 stages of K=128, 2 barriers; LDSM double-buffered 1 k8 ahead.
// B: direct GMEM fragments, double-buffered 1 k16 ahead.
// ---------------------------------------------------------------------------
__global__ void __launch_bounds__(THREADS) taylor_mma_kernel(
    float* __restrict__ out) {

    extern __shared__ char smem[];
    const uint32_t sb = smem_u32(smem);
    float* sred = (float*)(smem + 2 * STAGE_BYTES);

    const int tid  = threadIdx.x;
    const int lane = tid & 31, wid = tid >> 5;
    const int warpM = wid & 1, warpN = wid >> 1;   // 2 x 4 warps
    const int g = lane >> 2, tig = lane & 3;
    const int p0 = blockIdx.x * BM;
    const int b0 = blockIdx.y * BN;

    sred[tid] = 0.f;                               // BN == 256 == blockDim

    // ---- A cp.async coords (16KB sub-tile, 256 thr => 4 cp16/thread) ----
    const float* Ag = g_c3p + (size_t)p0 * DIMS;
    uint32_t cpdst[4];
    const float* cpsrc[4];
#pragma unroll
    for (int it = 0; it < 4; it++) {
        int idx = tid + it * THREADS;
        int row = idx >> 3, seg = idx & 7;
        cpdst[it] = row * 128 + ((seg ^ (row & 7)) << 4);
        cpsrc[it] = Ag + (size_t)row * DIMS + seg * 4;
    }
    auto cp_stage = [&](int stage) {
        const uint32_t s = sb + stage * STAGE_BYTES;
#pragma unroll
        for (int q = 0; q < 4; q++) {
            const int k0 = stage * 128 + q * 32;
#pragma unroll
            for (int it = 0; it < 4; it++)
                cp16(s + q * 16384 + cpdst[it], cpsrc[it] + k0);
        }
    };

    // ---- B fragment pointer; 8 n-slots per warp ----
    const uint4* bptr = (const uint4*)g_relf
                      + ((size_t)(b0 >> 3) + warpN * 8) * 512 + lane;

    // ---- LDSM addressing (within a 16KB sub-tile), 4 msl (M=64) ----
    int aoff[4], axor[4];
#pragma unroll
    for (int msl = 0; msl < 4; msl++) {
        int rowA = warpM * 64 + msl * 16 + ((lane >> 3) & 1) * 8 + (lane & 7);
        aoff[msl] = rowA * 128;
        axor[msl] = rowA & 7;
    }
    const int kcA = (lane >> 4) & 1;

    float acc[4][8][4];
#pragma unroll
    for (int m = 0; m < 4; m++)
#pragma unroll
        for (int n = 0; n < 8; n++)
#pragma unroll
            for (int r = 0; r < 4; r++) acc[m][n][r] = 0.f;

    uint32_t a[2][4][4];        // A k8 fragments, double-buffered
    uint4 Bb[2][8];             // B k16 fragments, double-buffered

    // prologue: both K halves in flight
    cp_stage(0); CP_COMMIT();
    cp_stage(1); CP_COMMIT();

    // A k8 LDSM: ss = k8 index within stage (0..15); q = ss>>2, ks8 = ss&3
#define LDSM_K8(AB, S, ss)                                                    \
    do {                                                                      \
        const uint32_t base_ = (S) + ((ss) >> 2) * 16384;                     \
        const int ks8_ = (ss) & 3;                                            \
        _Pragma("unroll")                                                     \
        for (int msl_ = 0; msl_ < 4; ++msl_)                                  \
            LDSM4((AB)[msl_], base_ + aoff[msl_] +                            \
                  ((((ks8_ << 1) | kcA) ^ axor[msl_]) << 4));                 \
    } while (0)

#define LDB(BB, kp)                                                           \
    do {                                                                      \
        _Pragma("unroll")                                                     \
        for (int nsl_ = 0; nsl_ < 8; nsl_++)                                  \
            (BB)[nsl_] = __ldg(bptr + nsl_ * 512 + (kp) * 32);                \
    } while (0)

    // 32 MMAs of one k8: half = k8 parity within the k16
#define MMA_K8(AB, BB, half)                                                  \
    do {                                                                      \
        _Pragma("unroll")                                                     \
        for (int nsl_ = 0; nsl_ < 8; ++nsl_) {                                \
            uint32_t b0v = (half) ? (BB)[nsl_].z : (BB)[nsl_].x;              \
            uint32_t b1v = (half) ? (BB)[nsl_].w : (BB)[nsl_].y;              \
            _Pragma("unroll")                                                 \
            for (int msl_ = 0; msl_ < 4; ++msl_)                              \
                MMA_TF32(acc[msl_][nsl_], (AB)[msl_][0], (AB)[msl_][1],       \
                         (AB)[msl_][2], (AB)[msl_][3], b0v, b1v);             \
        }                                                                     \
    } while (0)

    LDB(Bb[0], 0);
    CP_WAIT(1);
    __syncthreads();                       // barrier #1: stage 0 resident

#pragma unroll
    for (int stage = 0; stage < 2; ++stage) {
        const uint32_t S = sb + stage * STAGE_BYTES;
        LDSM_K8(a[0], S, 0);               // prime A pipeline for this stage
#pragma unroll
        for (int ss = 0; ss < 16; ++ss) {  // 16 k8 steps per stage
            const int gs = stage * 16 + ss;
            const int kp = gs >> 1;
            // prefetch next kp's B at the first k8 of each kp
            if ((gs & 1) == 0 && kp + 1 < 16) LDB(Bb[(kp + 1) & 1], kp + 1);
            // prefetch next k8's A fragments (same stage only)
            if (ss < 15) LDSM_K8(a[(ss + 1) & 1], S, ss + 1);
            // compute current k8
            MMA_K8(a[ss & 1], Bb[kp & 1], gs & 1);
        }
        if (stage == 0) {
            CP_WAIT(0);
            __syncthreads();               // barrier #2: stage 1 resident
        }
    }

    // ---- epilogue: sred[col] += sum_m D[m,col] * r_i(m)[b] * r_j(m)[b] ----
    const float* wi[4][2];
    const float* wj[4][2];
#pragma unroll
    for (int msl = 0; msl < 4; ++msl)
#pragma unroll
        for (int h = 0; h < 2; ++h) {
            int rloc = warpM * 64 + msl * 16 + h * 8 + g;
            uint32_t pij = g_pairIdx[p0 + rloc];
            wi[msl][h] = g_relT + (size_t)(pij >> 16) * BATCH + b0;
            wj[msl][h] = g_relT + (size_t)(pij & 0xFFFF) * BATCH + b0;
        }

#pragma unroll
    for (int nsl = 0; nsl < 8; ++nsl) {
        const int coln = warpN * 64 + nsl * 8 + tig * 2;
        float s0 = 0.f, s1 = 0.f;
#pragma unroll
        for (int msl = 0; msl < 4; ++msl) {
#pragma unroll
            for (int h = 0; h < 2; ++h) {
                float2 aw = *(const float2*)(wi[msl][h] + coln);
                float2 bw = *(const float2*)(wj[msl][h] + coln);
                s0 += acc[msl][nsl][2 * h]     * aw.x * bw.x;
                s1 += acc[msl][nsl][2 * h + 1] * aw.y * bw.y;
            }
        }
#pragma unroll
        for (int o = 4; o <= 16; o <<= 1) {
            s0 += __shfl_xor_sync(0xFFFFFFFFu, s0, o);
            s1 += __shfl_xor_sync(0xFFFFFFFFu, s1, o);
        }
        if (g == 0) {
            atomicAdd(&sred[coln],     s0);
            atomicAdd(&sred[coln + 1], s1);
        }
    }
    __syncthreads();

    atomicAdd(out + b0 + tid, sred[tid]);
}

// ---------------------------------------------------------------------------
extern "C" void kernel_launch(void* const* d_in, const int* in_sizes, int n_in,
                              void* d_out, int out_size) {
    const float* x       = (const float*)d_in[0];
    const float* offsets = (const float*)d_in[1];
    const float* coeff0  = (const float*)d_in[2];
    const float* coeff1  = (const float*)d_in[3];
    const float* coeff2  = (const float*)d_in[4];
    const float* coeff3  = (const float*)d_in[5];
    float* out = (float*)d_out;

    cudaFuncSetAttribute(taylor_mma_kernel,
                         cudaFuncAttributeMaxDynamicSharedMemorySize, SMEM_BYTES);

    prep_rel_kernel<<<((DIMS + 1) * BATCH) / 256, 256>>>(x, offsets, coeff0, out);

    dim3 pgrid(256, 258);
    pack_kernel<<<pgrid, 64>>>(coeff3, coeff2, coeff1);

    dim3 grid(NROWS / BM, BATCH / BN);   // (260, 8)
    taylor_mma_kernel<<<grid, THREADS, SMEM_BYTES>>>(out);
}

// round 14
// speedup vs baseline: 1.2819x; 1.2357x over previous
#include <cuda_runtime.h>
#include <cstdint>
#include <math.h>

#define DIMS   256
#define BATCH  2048
#define NPAIR  32896              // 256*257/2 multiset pairs (i<=j)
#define NROWS  33280              // 260 tiles * 128 rows
#define BM     128
#define BN     256
#define THREADS 512
#define STAGE_BYTES (BM * 32 * 4)                // 16 KB per 32-k chunk
#define SMEM_BYTES  (4 * STAGE_BYTES + BN * 4)   // ring of 4 + sred

// ---- device scratch (allocation-free) ----
// A rows: p = j(j+1)/2 + i for i<=j; S[p][k] = 0 for k<j, multiset-sym sum else.
__device__ float    g_c3p[NROWS * DIMS];         // 34 MB, tf32-rounded
__device__ uint32_t g_pairIdx[NROWS];            // (i<<16)|j per row
// B fragment-major: word = ((ng*16 + kp)*32 + lane)*4 + r
__device__ float    g_relf[BATCH * DIMS];        // 2 MB, tf32-rounded
__device__ float    g_relT[(DIMS + 1) * BATCH];  // rel^T exact; row 256 = 1.0

static __device__ __forceinline__ float f2tf32f(float f) {
    uint32_t r;
    asm("cvt.rna.tf32.f32 %0, %1;" : "=r"(r) : "f"(f));
    return __uint_as_float(r);
}

#define MMA_TF32(C, A0, A1, A2, A3, B0, B1)                                   \
    asm volatile(                                                             \
        "mma.sync.aligned.m16n8k8.row.col.f32.tf32.tf32.f32 "                 \
        "{%0,%1,%2,%3}, {%4,%5,%6,%7}, {%8,%9}, {%0,%1,%2,%3};"               \
        : "+f"((C)[0]), "+f"((C)[1]), "+f"((C)[2]), "+f"((C)[3])              \
        : "r"(A0), "r"(A1), "r"(A2), "r"(A3), "r"(B0), "r"(B1))

#define LDSM4(R, addr)                                                        \
    asm volatile("ldmatrix.sync.aligned.m8n8.x4.shared.b16 {%0,%1,%2,%3}, [%4];" \
        : "=r"((R)[0]), "=r"((R)[1]), "=r"((R)[2]), "=r"((R)[3])              \
        : "r"(addr))

static __device__ __forceinline__ void cp16(uint32_t dst, const void* gsrc) {
    asm volatile("cp.async.cg.shared.global [%0], [%1], 16;"
                 :: "r"(dst), "l"(gsrc) : "memory");
}
#define CP_COMMIT() asm volatile("cp.async.commit_group;" ::: "memory")
#define CP_WAIT2()  asm volatile("cp.async.wait_group 2;" ::: "memory")

static __device__ __forceinline__ uint32_t smem_u32(const void* p) {
    uint32_t a;
    asm("{ .reg .u64 t; cvta.to.shared.u64 t, %1; cvt.u32.u64 %0, t; }" : "=r"(a) : "l"(p));
    return a;
}

// ---------------------------------------------------------------------------
// Prep: g_relf fragments + g_relT weights + out init
// ---------------------------------------------------------------------------
__global__ void prep_rel_kernel(const float* __restrict__ x,
                                const float* __restrict__ offsets,
                                const float* __restrict__ c0p,
                                float* __restrict__ out) {
    int idx = blockIdx.x * blockDim.x + threadIdx.x;   // k*BATCH + b
    int k = idx / BATCH;
    int b = idx % BATCH;
    if (k < DIMS) {
        float r = x[b * DIMS + k] - offsets[k];
        g_relT[idx] = r;
        int ng = b >> 3, kp = k >> 4;
        int lane = (b & 7) * 4 + (k & 3);
        int rr = (((k >> 3) & 1) << 1) | ((k & 7) >> 2);
        ((uint32_t*)g_relf)[((ng * 16 + kp) * 32 + lane) * 4 + rr] =
            __float_as_uint(f2tf32f(r));
    } else {
        g_relT[idx] = 1.0f;
        out[b] = c0p[0];
    }
}

// ---------------------------------------------------------------------------
// pack3: full 3-index symmetrization into pair-rows with ragged K support.
// Block = (pair-range pr, k-range kr); 16^3 cubes, 6 permuted loads in SMEM.
// ---------------------------------------------------------------------------
__global__ void __launch_bounds__(256) pack3_kernel(const float* __restrict__ c3) {
    extern __shared__ float cub[];               // 6 * 4096 floats
    int pr = blockIdx.x;                          // 0..135, (I<=J) ranges
    int J = (int)((sqrtf(8.f * pr + 1.f) - 1.f) * 0.5f);
    while ((J + 1) * (J + 2) / 2 <= pr) J++;
    while (J * (J + 1) / 2 > pr) J--;
    int I = pr - J * (J + 1) / 2;
    int kr = blockIdx.y;                          // 0..15
    const int i0 = I * 16, j0 = J * 16, k0 = kr * 16;
    const int t = threadIdx.x;
    const int il = t >> 4, jl = t & 15;
    const int i = i0 + il, j = j0 + jl;
    const bool valid = (i <= j);
    const int p = (j * (j + 1)) / 2 + i;
    float* outrow = g_c3p + (size_t)p * DIMS + k0;
    if (valid && kr == 0) g_pairIdx[p] = ((uint32_t)i << 16) | (uint32_t)j;

    if (k0 + 15 < j0) {                           // whole block k < j: zeros
        if (valid) {
            float4 z = make_float4(0.f, 0.f, 0.f, 0.f);
            *(float4*)(outrow + 0) = z;  *(float4*)(outrow + 4) = z;
            *(float4*)(outrow + 8) = z;  *(float4*)(outrow + 12) = z;
        }
        return;
    }

    // load 6 permuted cubes: cube m axes = (R0, R1, R2) ranges
    const int R0[6] = { I, I, J, J, kr, kr };
    const int R1[6] = { J, kr, I, kr, I, J };
    const int R2[6] = { kr, J, kr, I, J, I };
#pragma unroll
    for (int m = 0; m < 6; m++) {
        const float* src = c3 + ((size_t)(R0[m] * 16 + il) * 65536)
                              + (R1[m] * 16 + jl) * 256 + R2[m] * 16;
        float* dst = cub + m * 4096 + il * 256 + jl * 16;
#pragma unroll
        for (int r4 = 0; r4 < 4; r4++) {
            float4 v = *(const float4*)(src + r4 * 4);
            dst[r4 * 4 + 0] = v.x; dst[r4 * 4 + 1] = v.y;
            dst[r4 * 4 + 2] = v.z; dst[r4 * 4 + 3] = v.w;
        }
    }
    __syncthreads();
    if (!valid) return;

    float S[16];
#pragma unroll
    for (int kl = 0; kl < 16; kl++) {
        int k = k0 + kl;
        float s;
        if (k < j) {
            s = 0.f;
        } else {
            float C1 = cub[0 * 4096 + il * 256 + jl * 16 + kl];   // c3[i,j,k]
            if (k == j) {
                if (i == j) s = C1;                               // c3[iii]
                else s = C1
                       + cub[2 * 4096 + jl * 256 + il * 16 + kl]  // c3[j,i,k]
                       + cub[3 * 4096 + jl * 256 + kl * 16 + il]; // c3[j,k,i]
            } else {
                float C2 = cub[1 * 4096 + il * 256 + kl * 16 + jl]; // c3[i,k,j]
                float C5 = cub[4 * 4096 + kl * 256 + il * 16 + jl]; // c3[k,i,j]
                if (i == j) s = C1 + C2 + C5;
                else s = C1 + C2 + C5
                       + cub[2 * 4096 + jl * 256 + il * 16 + kl]    // c3[j,i,k]
                       + cub[3 * 4096 + jl * 256 + kl * 16 + il]    // c3[j,k,i]
                       + cub[5 * 4096 + kl * 256 + jl * 16 + il];   // c3[k,j,i]
            }
        }
        S[kl] = f2tf32f(s);
    }
    *(float4*)(outrow + 0)  = *(float4*)&S[0];
    *(float4*)(outrow + 4)  = *(float4*)&S[4];
    *(float4*)(outrow + 8)  = *(float4*)&S[8];
    *(float4*)(outrow + 12) = *(float4*)&S[12];
}

// ---------------------------------------------------------------------------
// extras: c2 rows (weight r_j*1), c1 row (1*1), zero pads — full K support.
// ---------------------------------------------------------------------------
__global__ void extras_kernel(const float* __restrict__ c2,
                              const float* __restrict__ c1) {
    int r = blockIdx.x;            // 0..383
    int k = threadIdx.x;           // 0..255
    int p = NPAIR + r;
    float v;
    uint32_t pidx;
    if (r < 256)      { v = c2[r * DIMS + k]; pidx = (256u << 16) | (uint32_t)r; }
    else if (r == 256){ v = c1[k];            pidx = (256u << 16) | 256u; }
    else              { v = 0.f;              pidx = (256u << 16) | 256u; }
    g_c3p[(size_t)p * DIMS + k] = f2tf32f(v);
    if (k == 0) g_pairIdx[p] = pidx;
}

// ---------------------------------------------------------------------------
// Main (R10 schedule + per-tile chunk skipping): 512 thr, 16 warps 2Mx8N
// (64x32 warp tiles). A: cp.async 4-stage ring; B: direct GMEM fragments.
// ---------------------------------------------------------------------------
__global__ void __launch_bounds__(THREADS) taylor_mma_kernel(
    float* __restrict__ out) {

    extern __shared__ char smem[];
    const uint32_t sb = smem_u32(smem);
    float* sred = (float*)(smem + 4 * STAGE_BYTES);

    const int tid  = threadIdx.x;
    const int lane = tid & 31, wid = tid >> 5;
    const int warpM = wid & 1, warpN = wid >> 1;   // 2 x 8 warps
    const int g = lane >> 2, tig = lane & 3;

    // tile remap: extras tiles (257..259, full K) go first (LPT scheduling)
    int tile = blockIdx.x - 3;
    if (tile < 0) tile += 260;
    const int p0 = tile * BM;
    const int b0 = blockIdx.y * BN;

    // per-tile chunk start: c0 = floor(j_min / 32), j_min = j of first row
    int c0 = 0;
    if (tile < 257) {
        int r0 = tile * BM;
        int j0 = (int)((sqrtf(8.f * r0 + 1.f) - 1.f) * 0.5f);
        while ((j0 + 1) * (j0 + 2) / 2 <= r0) j0++;
        while (j0 * (j0 + 1) / 2 > r0) j0--;
        c0 = j0 >> 5;
    }

    if (tid < BN) sred[tid] = 0.f;

    // ---- A cp.async coords (16KB chunk, 512 thr => 2 cp16/thread) ----
    const float* Ag = g_c3p + (size_t)p0 * DIMS;
    uint32_t cpdst[2];
    const float* cpsrc[2];
#pragma unroll
    for (int it = 0; it < 2; it++) {
        int idx = tid + it * THREADS;
        int row = idx >> 3, seg = idx & 7;
        cpdst[it] = row * 128 + ((seg ^ (row & 7)) << 4);
        cpsrc[it] = Ag + (size_t)row * DIMS + seg * 4;
    }
    auto cp_chunk = [&](int c, int stage) {
        const uint32_t s = sb + stage * STAGE_BYTES;
        const int k0 = c * 32;
#pragma unroll
        for (int it = 0; it < 2; it++)
            cp16(s + cpdst[it], cpsrc[it] + k0);
    };

    // ---- B fragment pointer; 4 n-slots per warp ----
    const uint4* bptr = (const uint4*)g_relf
                      + ((size_t)(b0 >> 3) + warpN * 4) * 512 + lane;

    // ---- LDSM addressing ----
    int aoff[4], axor[4];
#pragma unroll
    for (int msl = 0; msl < 4; msl++) {
        int rowA = warpM * 64 + msl * 16 + ((lane >> 3) & 1) * 8 + (lane & 7);
        aoff[msl] = rowA * 128;
        axor[msl] = rowA & 7;
    }
    const int kcA = (lane >> 4) & 1;

    float acc[4][4][4];
#pragma unroll
    for (int m = 0; m < 4; m++)
#pragma unroll
        for (int n = 0; n < 4; n++)
#pragma unroll
            for (int r = 0; r < 4; r++) acc[m][n][r] = 0.f;

    uint4 Bb0[4], Bb1[4];

    // prologue: up to 3 chunks in flight (always 3 commits)
#pragma unroll
    for (int tq = 0; tq < 3; tq++) {
        if (c0 + tq < 8) cp_chunk(c0 + tq, (c0 + tq) & 3);
        CP_COMMIT();
    }

#define LDB(BB, kp)                                                           \
    do {                                                                      \
        _Pragma("unroll")                                                     \
        for (int nsl_ = 0; nsl_ < 4; nsl_++)                                  \
            (BB)[nsl_] = __ldg(bptr + nsl_ * 512 + (kp) * 32);                \
    } while (0)

#define COMPUTE_KP(As, KSBASE, BB)                                            \
    do {                                                                      \
        _Pragma("unroll")                                                     \
        for (int ks2 = 0; ks2 < 2; ++ks2) {                                   \
            const int ks = (KSBASE) + ks2;                                    \
            uint32_t a[4][4];                                                 \
            _Pragma("unroll")                                                 \
            for (int msl = 0; msl < 4; ++msl)                                 \
                LDSM4(a[msl], (As) + aoff[msl] +                              \
                      ((((ks << 1) | kcA) ^ axor[msl]) << 4));                \
            _Pragma("unroll")                                                 \
            for (int nsl = 0; nsl < 4; ++nsl) {                               \
                uint32_t b0v = ks2 ? (BB)[nsl].z : (BB)[nsl].x;               \
                uint32_t b1v = ks2 ? (BB)[nsl].w : (BB)[nsl].y;               \
                _Pragma("unroll")                                             \
                for (int msl = 0; msl < 4; ++msl)                             \
                    MMA_TF32(acc[msl][nsl], a[msl][0], a[msl][1],             \
                             a[msl][2], a[msl][3], b0v, b1v);                 \
            }                                                                 \
        }                                                                     \
    } while (0)

    LDB(Bb0, 2 * c0);

    for (int cc = c0; cc < 8; ++cc) {
        CP_WAIT2();
        __syncthreads();
        if (cc + 3 < 8) cp_chunk(cc + 3, (cc + 3) & 3);
        CP_COMMIT();

        const uint32_t As = sb + (cc & 3) * STAGE_BYTES;
        const int s0 = 2 * cc;

        LDB(Bb1, s0 + 1);
        COMPUTE_KP(As, 0, Bb0);
        if (cc + 1 < 8) LDB(Bb0, s0 + 2);
        COMPUTE_KP(As, 2, Bb1);
    }

    // ---- epilogue: sred[col] += sum_m D[m,col] * r_i(m)[b] * r_j(m)[b] ----
    const float* wi[4][2];
    const float* wj[4][2];
#pragma unroll
    for (int msl = 0; msl < 4; ++msl)
#pragma unroll
        for (int h = 0; h < 2; ++h) {
            int rloc = warpM * 64 + msl * 16 + h * 8 + g;
            uint32_t pij = g_pairIdx[p0 + rloc];
            wi[msl][h] = g_relT + (size_t)(pij >> 16) * BATCH + b0;
            wj[msl][h] = g_relT + (size_t)(pij & 0xFFFF) * BATCH + b0;
        }

#pragma unroll
    for (int nsl = 0; nsl < 4; ++nsl) {
        const int coln = warpN * 32 + nsl * 8 + tig * 2;
        float s0 = 0.f, s1 = 0.f;
#pragma unroll
        for (int msl = 0; msl < 4; ++msl) {
#pragma unroll
            for (int h = 0; h < 2; ++h) {
                float2 aw = *(const float2*)(wi[msl][h] + coln);
                float2 bw = *(const float2*)(wj[msl][h] + coln);
                s0 += acc[msl][nsl][2 * h]     * aw.x * bw.x;
                s1 += acc[msl][nsl][2 * h + 1] * aw.y * bw.y;
            }
        }
#pragma unroll
        for (int o = 4; o <= 16; o <<= 1) {
            s0 += __shfl_xor_sync(0xFFFFFFFFu, s0, o);
            s1 += __shfl_xor_sync(0xFFFFFFFFu, s1, o);
        }
        if (g == 0) {
            atomicAdd(&sred[coln],     s0);
            atomicAdd(&sred[coln + 1], s1);
        }
    }
    __syncthreads();

    if (tid < BN) atomicAdd(out + b0 + tid, sred[tid]);
}

// ---------------------------------------------------------------------------
extern "C" void kernel_launch(void* const* d_in, const int* in_sizes, int n_in,
                              void* d_out, int out_size) {
    const float* x       = (const float*)d_in[0];
    const float* offsets = (const float*)d_in[1];
    const float* coeff0  = (const float*)d_in[2];
    const float* coeff1  = (const float*)d_in[3];
    const float* coeff2  = (const float*)d_in[4];
    const float* coeff3  = (const float*)d_in[5];
    float* out = (float*)d_out;

    cudaFuncSetAttribute(taylor_mma_kernel,
                         cudaFuncAttributeMaxDynamicSharedMemorySize, SMEM_BYTES);
    cudaFuncSetAttribute(pack3_kernel,
                         cudaFuncAttributeMaxDynamicSharedMemorySize, 98304);

    prep_rel_kernel<<<((DIMS + 1) * BATCH) / 256, 256>>>(x, offsets, coeff0, out);

    dim3 pgrid(136, 16);
    pack3_kernel<<<pgrid, 256, 98304>>>(coeff3);
    extras_kernel<<<384, 256>>>(coeff2, coeff1);

    dim3 grid(NROWS / BM, BATCH / BN);   // (260, 8)
    taylor_mma_kernel<<<grid, THREADS, SMEM_BYTES>>>(out);
}